// round 9
// baseline (speedup 1.0000x reference)
#include <cuda_runtime.h>
#include <math.h>

#define Dd 2048
#define Hh 1152
#define Kk 64
#define NAa 18
#define Rr 10

// block index map (dependency-ordered)
#define S0    0      // 256: s rows (8/block)
#define W0    256    // 576: worker gates (2 units/block)
#define HS0   832    // 8: hsum
#define GS0   840    // 8: goalsum
#define TB0   848    // 8: T columns            [spin u]
#define COSB  856    // 1: cosines r=0..8       [spin s]
#define WVB   857    // 1: w_value              [spin u]
#define GP0   858    // 1024: Whh_m -> gpart
#define M0    1882   // 1024: Wih_m + gpart     [spin s, gpart]
#define EPI   2906   // 1: epilogue             [spin all]
#define NBLK  2907

// ---------------- scratch (device globals) ----------------------------------
__device__ __align__(16) float d_s[Dd];
__device__ __align__(16) float d_u[Hh];
__device__ __align__(16) float d_gpart[4 * Dd];
__device__ __align__(16) float d_gact[4 * Dd];
__device__ __align__(16) float d_T[NAa * Dd];
__device__ __align__(16) float d_hsum[Dd];
__device__ __align__(16) float d_goalsum[Dd];
__device__ float d_cosv[Rr];
__device__ float d_wval;
__device__ int d_sdone, d_udone, d_gpdone, d_mdone, d_tdone, d_auxdone, d_hgdone;

__device__ __forceinline__ float sigm(float x) { return 1.f / (1.f + expf(-x)); }

template <int NIT>
__device__ __forceinline__ float wdot(const float4* __restrict__ a,
                                      const float4* __restrict__ b, int lane) {
    float acc = 0.f;
#pragma unroll
    for (int i = 0; i < NIT; i++) {
        float4 x = a[lane + i * 32];
        float4 y = b[lane + i * 32];
        acc = fmaf(x.x, y.x, acc);
        acc = fmaf(x.y, y.y, acc);
        acc = fmaf(x.z, y.z, acc);
        acc = fmaf(x.w, y.w, acc);
    }
#pragma unroll
    for (int o = 16; o; o >>= 1) acc += __shfl_xor_sync(0xffffffffu, acc, o);
    return acc;
}

__device__ __forceinline__ void wait_ctr(int* ctr, int tgt) {
    if (threadIdx.x == 0) {
        volatile int* c = ctr;
        while (*c < tgt) __nanosleep(64);
        __threadfence();
    }
    __syncthreads();
}

// ---------------- the one kernel ---------------------------------------------
__global__ void __launch_bounds__(256)
fun_one(const float* __restrict__ x, const float* __restrict__ Wp,
        const float* __restrict__ bp, const float* __restrict__ Wms,
        const float* __restrict__ bms, const float* __restrict__ Wih_m,
        const float* __restrict__ Whh_m, const float* __restrict__ bih_m,
        const float* __restrict__ bhh_m, const float* __restrict__ hn_m,
        const float* __restrict__ cn_m, const float* __restrict__ Wmv,
        const float* __restrict__ bmv, const float* __restrict__ Wih_w,
        const float* __restrict__ Whh_w, const float* __restrict__ bih_w,
        const float* __restrict__ bhh_w, const float* __restrict__ hn_w,
        const float* __restrict__ cn_w, const float* __restrict__ Wphi,
        const float* __restrict__ Wc, const float* __restrict__ bc,
        const float* __restrict__ states, const float* __restrict__ goals,
        const int* __restrict__ tickp, float* __restrict__ out) {
    const int tid = threadIdx.x;
    const int warp = tid >> 5, lane = tid & 31;
    const int b = blockIdx.x;
    __shared__ __align__(16) float sm[4096];
    __shared__ float gsh[8];
    __shared__ float red[256];
    __shared__ float sc[4];

    if (b < W0) {
        // ---- s: z in smem, 8 rows ----
        float x0 = x[0], x1 = x[1];
        for (int i = tid; i < Dd; i += 256) {
            float v = fmaf(Wp[2 * i], x0, fmaf(Wp[2 * i + 1], x1, bp[i]));
            sm[i] = fmaxf(v, 0.f);
        }
        __syncthreads();
        int row = b * 8 + warp;
        float v = wdot<16>((const float4*)(Wms + (size_t)row * Dd),
                           (const float4*)sm, lane);
        if (!lane) {
            d_s[row] = fmaxf(v + bms[row], 0.f);
            __threadfence();
        }
        __syncthreads();
        if (tid == 0) atomicAdd(&d_sdone, 1);
    } else if (b < HS0) {
        // ---- worker: z in smem, 2 units ----
        float x0 = x[0], x1 = x[1];
        for (int i = tid; i < Dd; i += 256) {
            float v = fmaf(Wp[2 * i], x0, fmaf(Wp[2 * i + 1], x1, bp[i]));
            sm[i] = fmaxf(v, 0.f);
        }
        __syncthreads();
        const int unit = (b - W0) * 2 + (warp >> 2);
        const int q = warp & 3;
        const int row = unit + q * Hh;
        float a = wdot<16>((const float4*)(Wih_w + (size_t)row * Dd),
                           (const float4*)sm, lane);
        float cc = wdot<9>((const float4*)(Whh_w + (size_t)row * Hh),
                           (const float4*)hn_w, lane);
        if (!lane) gsh[warp] = a + cc + bih_w[row] + bhh_w[row];
        __syncthreads();
        if ((tid & 127) == 0) {
            const int half = tid >> 7;
            const int j = (b - W0) * 2 + half;
            const float* g = gsh + half * 4;
            float ig = sigm(g[0]), fg = sigm(g[1]);
            float g2 = tanhf(g[2]), og = sigm(g[3]);
            float c2 = fmaf(fg, cn_w[j], ig * g2);
            d_u[j] = og * tanhf(c2);
            __threadfence();
        }
        __syncthreads();
        if (tid == 0) atomicAdd(&d_udone, 1);
    } else if (b < GS0) {
        const int i = (b - HS0) * 256 + tid;
        float a = 0.f;
#pragma unroll
        for (int r = 0; r < Rr; r++) a += hn_m[(size_t)r * Dd + i];
        d_hsum[i] = a;
        __threadfence();
        __syncthreads();
        if (tid == 0) atomicAdd(&d_hgdone, 1);
    } else if (b < TB0) {
        const int d = (b - GS0) * 256 + tid;
        float a = 0.f;
#pragma unroll
        for (int r = 1; r < Rr; r++) a += goals[(size_t)r * Dd + d];
        d_goalsum[d] = a;
        __threadfence();
        __syncthreads();
        if (tid == 0) atomicAdd(&d_hgdone, 1);
    } else if (b < COSB) {
        // ---- T columns, k-unrolled x4 ----
        wait_ctr(&d_udone, 576);
        for (int i = tid; i < NAa * Kk; i += 256) sm[i] = d_u[i];
        __syncthreads();
        const int d = (b - TB0) * 256 + tid;
        float acc[NAa];
#pragma unroll
        for (int a = 0; a < NAa; a++) acc[a] = 0.f;
        for (int k = 0; k < Kk; k += 4) {
            float w0 = Wphi[(size_t)(k + 0) * Dd + d];
            float w1 = Wphi[(size_t)(k + 1) * Dd + d];
            float w2 = Wphi[(size_t)(k + 2) * Dd + d];
            float w3 = Wphi[(size_t)(k + 3) * Dd + d];
#pragma unroll
            for (int a = 0; a < NAa; a++) {
                float t = fmaf(sm[a * Kk + k], w0, acc[a]);
                t = fmaf(sm[a * Kk + k + 1], w1, t);
                t = fmaf(sm[a * Kk + k + 2], w2, t);
                acc[a] = fmaf(sm[a * Kk + k + 3], w3, t);
            }
        }
#pragma unroll
        for (int a = 0; a < NAa; a++) d_T[(size_t)a * Dd + d] = acc[a];
        __threadfence();
        __syncthreads();
        if (tid == 0) atomicAdd(&d_tdone, 1);
    } else if (b == COSB) {
        wait_ctr(&d_sdone, 256);
        for (int r = warp; r < Rr - 1; r += 8) {
            const float* st = states + (size_t)(r + 1) * Dd;
            const float* gl = goals + (size_t)(r + 1) * Dd;
            float num = 0.f, dd = 0.f, gg = 0.f;
            for (int d = lane; d < Dd; d += 32) {
                float diff = d_s[d] - st[d];
                float go = gl[d];
                num = fmaf(diff, go, num);
                dd = fmaf(diff, diff, dd);
                gg = fmaf(go, go, gg);
            }
#pragma unroll
            for (int o = 16; o; o >>= 1) {
                num += __shfl_xor_sync(0xffffffffu, num, o);
                dd += __shfl_xor_sync(0xffffffffu, dd, o);
                gg += __shfl_xor_sync(0xffffffffu, gg, o);
            }
            if (!lane) {
                d_cosv[r] = num / (fmaxf(sqrtf(dd), 1e-8f) *
                                   fmaxf(sqrtf(gg), 1e-8f));
                __threadfence();
            }
        }
        __syncthreads();
        if (tid == 0) atomicAdd(&d_auxdone, 1);
    } else if (b == WVB) {
        wait_ctr(&d_udone, 576);
        float wv = 0.f;
        for (int j = tid; j < Hh; j += 256) wv = fmaf(d_u[j], Wc[j], wv);
        red[tid] = wv;
        __syncthreads();
        for (int s = 128; s; s >>= 1) {
            if (tid < s) red[tid] += red[tid + s];
            __syncthreads();
        }
        if (tid == 0) {
            d_wval = red[0] + bc[0];
            __threadfence();
            atomicAdd(&d_auxdone, 1);
        }
    } else if (b < M0) {
        // ---- Whh_m rows -> gpart (no dependency) ----
        const int tick = *tickp;
        const int row = (b - GP0) * 8 + warp;
        float v = wdot<16>((const float4*)(Whh_m + (size_t)row * Dd),
                           (const float4*)(hn_m + (size_t)tick * Dd), lane);
        if (!lane) {
            d_gpart[row] = v + bih_m[row] + bhh_m[row];
            __threadfence();
        }
        __syncthreads();
        if (tid == 0) atomicAdd(&d_gpdone, 1);
    } else if (b < EPI) {
        // ---- Wih_m rows + gpart -> gact ----
        wait_ctr(&d_sdone, 256);
        wait_ctr(&d_gpdone, 1024);
        const int row = (b - M0) * 8 + warp;
        float v = wdot<16>((const float4*)(Wih_m + (size_t)row * Dd),
                           (const float4*)d_s, lane);
        if (!lane) {
            d_gact[row] = v + d_gpart[row];
            __threadfence();
        }
        __syncthreads();
        if (tid == 0) atomicAdd(&d_mdone, 1);
    } else {
        // ---- epilogue ----
        wait_ctr(&d_mdone, 1024);
        wait_ctr(&d_tdone, 8);
        wait_ctr(&d_auxdone, 2);
        wait_ctr(&d_hgdone, 16);

        const int tick = *tickp;
        float* ghat = sm;
        float* gsum = sm + 2048;
        float acc_sq = 0.f, acc_mv = 0.f;
#pragma unroll
        for (int rep = 0; rep < 8; rep++) {
            const int i = tid + rep * 256;
            float g0 = d_gact[i];
            float g1 = d_gact[i + Dd];
            float g2 = d_gact[i + 2 * Dd];
            float g3 = d_gact[i + 3 * Dd];
            float ig = sigm(g0), fg = sigm(g1);
            float gt = tanhf(g2), og = sigm(g3);
            float c2 = fmaf(fg, cn_m[(size_t)tick * Dd + i], ig * gt);
            float hnew = og * tanhf(c2);
            float hs = d_hsum[i] - hn_m[(size_t)tick * Dd + i] + hnew;
            float gh = hs * 0.1f;
            ghat[i] = gh;
            acc_sq = fmaf(gh, gh, acc_sq);
            acc_mv = fmaf(gh, Wmv[i], acc_mv);
        }
#pragma unroll
        for (int o = 16; o; o >>= 1) {
            acc_sq += __shfl_xor_sync(0xffffffffu, acc_sq, o);
            acc_mv += __shfl_xor_sync(0xffffffffu, acc_mv, o);
        }
        if (!lane) { red[warp] = acc_sq; red[warp + 8] = acc_mv; }
        __syncthreads();
        if (tid == 0) {
            float sa = 0.f, sb = 0.f;
#pragma unroll
            for (int q = 0; q < 8; q++) { sa += red[q]; sb += red[q + 8]; }
            sc[0] = 1.f / fmaxf(sqrtf(sa), 1e-12f);
            sc[1] = sb;
        }
        __syncthreads();
        const float inv_norm = sc[0];
        for (int d = tid; d < Dd; d += 256)
            gsum[d] = fmaf(ghat[d], inv_norm, d_goalsum[d]);
        __syncthreads();

        for (int a = warp; a < NAa; a += 8) {
            float v = wdot<16>((const float4*)(d_T + (size_t)a * Dd),
                               (const float4*)gsum, lane);
            if (!lane) out[a] = v;
        }
        if (warp == 0) {
            const float* st = states + (size_t)Rr * Dd;
            float num = 0.f, dd = 0.f, gg = 0.f;
            for (int d = lane; d < Dd; d += 32) {
                float diff = d_s[d] - st[d];
                float go = ghat[d] * inv_norm;
                num = fmaf(diff, go, num);
                dd = fmaf(diff, diff, dd);
                gg = fmaf(go, go, gg);
            }
#pragma unroll
            for (int o = 16; o; o >>= 1) {
                num += __shfl_xor_sync(0xffffffffu, num, o);
                dd += __shfl_xor_sync(0xffffffffu, dd, o);
                gg += __shfl_xor_sync(0xffffffffu, gg, o);
            }
            if (!lane)
                sc[2] = num / (fmaxf(sqrtf(dd), 1e-8f) *
                               fmaxf(sqrtf(gg), 1e-8f));
        }
        __syncthreads();
        if (tid == 0) {
            float cs = sc[2];
#pragma unroll
            for (int r = 0; r < Rr - 1; r++) cs += d_cosv[r];
            out[18] = 2048.f * cs * 0.1f;
            out[19] = d_wval;
            out[20] = sc[1] + bmv[0];
            // reset counters for next graph replay
            d_sdone = 0; d_udone = 0; d_gpdone = 0; d_mdone = 0;
            d_tdone = 0; d_auxdone = 0; d_hgdone = 0;
        }
    }
}

// ---------------- launch ------------------------------------------------------
extern "C" void kernel_launch(void* const* d_in, const int* in_sizes, int n_in,
                              void* d_out, int out_size) {
    const float* x      = (const float*)d_in[0];
    const float* Wp     = (const float*)d_in[1];
    const float* bp     = (const float*)d_in[2];
    const float* Wms    = (const float*)d_in[3];
    const float* bms    = (const float*)d_in[4];
    const float* Wih_m  = (const float*)d_in[5];
    const float* Whh_m  = (const float*)d_in[6];
    const float* bih_m  = (const float*)d_in[7];
    const float* bhh_m  = (const float*)d_in[8];
    const float* hn_m   = (const float*)d_in[9];
    const float* cn_m   = (const float*)d_in[10];
    const float* Wmv    = (const float*)d_in[11];
    const float* bmv    = (const float*)d_in[12];
    const float* Wih_w  = (const float*)d_in[13];
    const float* Whh_w  = (const float*)d_in[14];
    const float* bih_w  = (const float*)d_in[15];
    const float* bhh_w  = (const float*)d_in[16];
    const float* hn_w   = (const float*)d_in[17];
    const float* cn_w   = (const float*)d_in[18];
    const float* Wphi   = (const float*)d_in[19];
    const float* Wc     = (const float*)d_in[20];
    const float* bc     = (const float*)d_in[21];
    const float* states = (const float*)d_in[22];
    const float* goals  = (const float*)d_in[23];
    const int*   tick   = (const int*)d_in[24];
    float* out = (float*)d_out;

    fun_one<<<NBLK, 256>>>(x, Wp, bp, Wms, bms, Wih_m, Whh_m, bih_m, bhh_m,
                           hn_m, cn_m, Wmv, bmv, Wih_w, Whh_w, bih_w, bhh_w,
                           hn_w, cn_w, Wphi, Wc, bc, states, goals, tick, out);
}

// round 10
// speedup vs baseline: 1.3759x; 1.3759x over previous
#include <cuda_runtime.h>
#include <math.h>

#define Dd 2048
#define Hh 1152
#define Kk 64
#define NAa 18
#define Rr 10

// ---------------- scratch (device globals) ----------------------------------
__device__ __align__(16) float d_s[Dd];
__device__ __align__(16) float d_u[Hh];
__device__ __align__(16) float d_gpart[4 * Dd];   // Whh_m@h_t + biases
__device__ __align__(16) float d_gact[4 * Dd];    // full manager gate preact
__device__ __align__(16) float d_hsum[Dd];        // sum_r hn_m[r]
__device__ __align__(16) float d_goalsum[Dd];     // sum_{r=1..9} goals[r]
__device__ float d_cosv[Rr];
__device__ float d_wval;

__device__ __forceinline__ float sigm(float x) { return 1.f / (1.f + expf(-x)); }

// warp dot over NIT*32 float4s (lane-strided), result on all lanes
template <int NIT>
__device__ __forceinline__ float wdot(const float4* __restrict__ a,
                                      const float4* __restrict__ b, int lane) {
    float acc = 0.f;
#pragma unroll
    for (int i = 0; i < NIT; i++) {
        float4 x = a[lane + i * 32];
        float4 y = b[lane + i * 32];
        acc = fmaf(x.x, y.x, acc);
        acc = fmaf(x.y, y.y, acc);
        acc = fmaf(x.z, y.z, acc);
        acc = fmaf(x.w, y.w, acc);
    }
#pragma unroll
    for (int o = 16; o; o >>= 1) acc += __shfl_xor_sync(0xffffffffu, acc, o);
    return acc;
}

// ---------------- k1 (= proven kA): wave 1 -----------------------------------
// blocks [0,256):      s rows, 1 row/warp (z recomputed in smem)
// blocks [256,832):    worker gate rows, 1 row/warp, 2 units/block
// blocks [832,1856):   Whh_m rows -> d_gpart, 1 row/warp
// blocks [1856,1864):  hsum
// blocks [1864,1872):  goalsum
__global__ void __launch_bounds__(256)
k1(const float* __restrict__ x, const float* __restrict__ Wp,
   const float* __restrict__ bp, const float* __restrict__ Wms,
   const float* __restrict__ bms, const float* __restrict__ Wih_w,
   const float* __restrict__ Whh_w, const float* __restrict__ bih_w,
   const float* __restrict__ bhh_w, const float* __restrict__ hn_w,
   const float* __restrict__ cn_w, const float* __restrict__ Whh_m,
   const float* __restrict__ bih_m, const float* __restrict__ bhh_m,
   const float* __restrict__ hn_m, const float* __restrict__ goals,
   const int* __restrict__ tickp) {
    const int warp = threadIdx.x >> 5, lane = threadIdx.x & 31;
    const int b = blockIdx.x;
    __shared__ __align__(16) float zs[Dd];
    __shared__ float gsh[8];

    if (b < 832) {
        float x0 = x[0], x1 = x[1];
        for (int i = threadIdx.x; i < Dd; i += 256) {
            float v = fmaf(Wp[2 * i], x0, fmaf(Wp[2 * i + 1], x1, bp[i]));
            zs[i] = fmaxf(v, 0.f);
        }
        __syncthreads();
        if (b < 256) {
            int row = b * 8 + warp;
            float v = wdot<16>((const float4*)(Wms + (size_t)row * Dd),
                               (const float4*)zs, lane);
            if (!lane) d_s[row] = fmaxf(v + bms[row], 0.f);
        } else {
            const int wb = b - 256;
            const int unit = wb * 2 + (warp >> 2);
            const int q = warp & 3;
            const int row = unit + q * Hh;
            float a = wdot<16>((const float4*)(Wih_w + (size_t)row * Dd),
                               (const float4*)zs, lane);
            float c = wdot<9>((const float4*)(Whh_w + (size_t)row * Hh),
                              (const float4*)hn_w, lane);
            if (!lane) gsh[warp] = a + c + bih_w[row] + bhh_w[row];
            __syncthreads();
            if ((threadIdx.x & 127) == 0) {
                const int half = threadIdx.x >> 7;
                const int j = wb * 2 + half;
                const float* g = gsh + half * 4;
                float ig = sigm(g[0]), fg = sigm(g[1]);
                float g2 = tanhf(g[2]), og = sigm(g[3]);
                float c2 = fmaf(fg, cn_w[j], ig * g2);
                d_u[j] = og * tanhf(c2);
            }
        }
    } else if (b < 1856) {
        const int tick = *tickp;
        const int row = (b - 832) * 8 + warp;
        float v = wdot<16>((const float4*)(Whh_m + (size_t)row * Dd),
                           (const float4*)(hn_m + (size_t)tick * Dd), lane);
        if (!lane) d_gpart[row] = v + bih_m[row] + bhh_m[row];
    } else if (b < 1864) {
        const int i = (b - 1856) * 256 + threadIdx.x;
        float a = 0.f;
#pragma unroll
        for (int r = 0; r < Rr; r++) a += hn_m[(size_t)r * Dd + i];
        d_hsum[i] = a;
    } else {
        const int d = (b - 1864) * 256 + threadIdx.x;
        float a = 0.f;
#pragma unroll
        for (int r = 1; r < Rr; r++) a += goals[(size_t)r * Dd + d];
        d_goalsum[d] = a;
    }
}

// ---------------- k2: wave 2 --------------------------------------------------
// blocks [0,1024): Wih_m rows (1/warp) + gpart -> gact   (pure streaming)
// block  1024:     cosines r=0..8
// block  1025:     w_value
__global__ void __launch_bounds__(256)
k2(const float* __restrict__ Wih_m, const float* __restrict__ goals,
   const float* __restrict__ states, const float* __restrict__ Wc,
   const float* __restrict__ bc) {
    const int tid = threadIdx.x;
    const int warp = tid >> 5, lane = tid & 31;
    const int b = blockIdx.x;

    if (b < 1024) {
        const int row = b * 8 + warp;
        float v = wdot<16>((const float4*)(Wih_m + (size_t)row * Dd),
                           (const float4*)d_s, lane);
        if (!lane) d_gact[row] = v + d_gpart[row];
    } else if (b == 1024) {
        for (int r = warp; r < Rr - 1; r += 8) {
            const float* st = states + (size_t)(r + 1) * Dd;
            const float* gl = goals + (size_t)(r + 1) * Dd;
            float num = 0.f, dd = 0.f, gg = 0.f;
            for (int d = lane; d < Dd; d += 32) {
                float diff = d_s[d] - st[d];
                float go = gl[d];
                num = fmaf(diff, go, num);
                dd = fmaf(diff, diff, dd);
                gg = fmaf(go, go, gg);
            }
#pragma unroll
            for (int o = 16; o; o >>= 1) {
                num += __shfl_xor_sync(0xffffffffu, num, o);
                dd += __shfl_xor_sync(0xffffffffu, dd, o);
                gg += __shfl_xor_sync(0xffffffffu, gg, o);
            }
            if (!lane)
                d_cosv[r] = num / (fmaxf(sqrtf(dd), 1e-8f) *
                                   fmaxf(sqrtf(gg), 1e-8f));
        }
    } else {
        __shared__ float red[256];
        float wv = 0.f;
        for (int j = tid; j < Hh; j += 256) wv = fmaf(d_u[j], Wc[j], wv);
        red[tid] = wv;
        __syncthreads();
        for (int s = 128; s; s >>= 1) {
            if (tid < s) red[tid] += red[tid + s];
            __syncthreads();
        }
        if (tid == 0) d_wval = red[0] + bc[0];
    }
}

// ---------------- k3: final (1 block, 1024 threads) ---------------------------
// pointwise manager cell + norms + gsum + w=Wphi@gsum + logits + outputs
// out: [0:18] logits, [18] intrinsic, [19] w_value, [20] m_value
__global__ void __launch_bounds__(1024)
k3(const float* __restrict__ hn_m, const float* __restrict__ cn_m,
   const float* __restrict__ Wmv, const float* __restrict__ Wphi,
   const float* __restrict__ states, const float* __restrict__ bmv,
   const int* __restrict__ tickp, float* __restrict__ out) {
    const int tid = threadIdx.x;
    const int warp = tid >> 5, lane = tid & 31;
    __shared__ float red[64];
    __shared__ float sc[4];
    __shared__ float wvec[Kk];
    __shared__ __align__(16) float ghat_s[Dd];
    __shared__ __align__(16) float gsum[Dd];

    const int tick = *tickp;
    float acc_sq = 0.f, acc_mv = 0.f;
#pragma unroll
    for (int rep = 0; rep < 2; rep++) {
        const int i = tid + rep * 1024;
        float g0 = d_gact[i];
        float g1 = d_gact[i + Dd];
        float g2 = d_gact[i + 2 * Dd];
        float g3 = d_gact[i + 3 * Dd];
        float ig = sigm(g0), fg = sigm(g1);
        float gt = tanhf(g2), og = sigm(g3);
        float c2 = fmaf(fg, cn_m[(size_t)tick * Dd + i], ig * gt);
        float hnew = og * tanhf(c2);
        float hs = d_hsum[i] - hn_m[(size_t)tick * Dd + i] + hnew;
        float gh = hs * 0.1f;
        ghat_s[i] = gh;
        acc_sq = fmaf(gh, gh, acc_sq);
        acc_mv = fmaf(gh, Wmv[i], acc_mv);
    }
#pragma unroll
    for (int o = 16; o; o >>= 1) {
        acc_sq += __shfl_xor_sync(0xffffffffu, acc_sq, o);
        acc_mv += __shfl_xor_sync(0xffffffffu, acc_mv, o);
    }
    if (!lane) { red[warp] = acc_sq; red[warp + 32] = acc_mv; }
    __syncthreads();
    if (tid == 0) {
        float sa = 0.f, sb = 0.f;
#pragma unroll
        for (int q = 0; q < 32; q++) { sa += red[q]; sb += red[q + 32]; }
        sc[0] = 1.f / fmaxf(sqrtf(sa), 1e-12f);
        sc[1] = sb;
    }
    __syncthreads();

    const float inv_norm = sc[0];
    for (int d = tid; d < Dd; d += 1024)
        gsum[d] = fmaf(ghat_s[d], inv_norm, d_goalsum[d]);
    __syncthreads();

    // w = Wphi @ gsum : 64 rows, 2 per warp (32 warps)
#pragma unroll
    for (int rep = 0; rep < 2; rep++) {
        const int k = warp + rep * 32;
        float v = wdot<16>((const float4*)(Wphi + (size_t)k * Dd),
                           (const float4*)gsum, lane);
        if (!lane) wvec[k] = v;
    }
    __syncthreads();

    // logits[a] = u[a*64 .. a*64+63] . wvec   (warps 0..17, 2 elems/lane)
    if (warp < NAa) {
        float v = fmaf(d_u[warp * Kk + lane], wvec[lane],
                       d_u[warp * Kk + 32 + lane] * wvec[32 + lane]);
#pragma unroll
        for (int o = 16; o; o >>= 1) v += __shfl_xor_sync(0xffffffffu, v, o);
        if (!lane) out[warp] = v;
    } else if (warp == NAa) {
        // last cosine (r = 9, goal = g)
        const float* st = states + (size_t)Rr * Dd;
        float num = 0.f, dd = 0.f, gg = 0.f;
        for (int d = lane; d < Dd; d += 32) {
            float diff = d_s[d] - st[d];
            float go = ghat_s[d] * inv_norm;
            num = fmaf(diff, go, num);
            dd = fmaf(diff, diff, dd);
            gg = fmaf(go, go, gg);
        }
#pragma unroll
        for (int o = 16; o; o >>= 1) {
            num += __shfl_xor_sync(0xffffffffu, num, o);
            dd += __shfl_xor_sync(0xffffffffu, dd, o);
            gg += __shfl_xor_sync(0xffffffffu, gg, o);
        }
        if (!lane)
            sc[2] = num / (fmaxf(sqrtf(dd), 1e-8f) * fmaxf(sqrtf(gg), 1e-8f));
    }
    __syncthreads();
    if (tid == 0) {
        float cs = sc[2];
#pragma unroll
        for (int r = 0; r < Rr - 1; r++) cs += d_cosv[r];
        out[18] = 2048.f * cs * 0.1f;
        out[19] = d_wval;
        out[20] = sc[1] + bmv[0];
    }
}

// ---------------- launch ------------------------------------------------------
extern "C" void kernel_launch(void* const* d_in, const int* in_sizes, int n_in,
                              void* d_out, int out_size) {
    const float* x      = (const float*)d_in[0];
    const float* Wp     = (const float*)d_in[1];
    const float* bp     = (const float*)d_in[2];
    const float* Wms    = (const float*)d_in[3];
    const float* bms    = (const float*)d_in[4];
    const float* Wih_m  = (const float*)d_in[5];
    const float* Whh_m  = (const float*)d_in[6];
    const float* bih_m  = (const float*)d_in[7];
    const float* bhh_m  = (const float*)d_in[8];
    const float* hn_m   = (const float*)d_in[9];
    const float* cn_m   = (const float*)d_in[10];
    const float* Wmv    = (const float*)d_in[11];
    const float* bmv    = (const float*)d_in[12];
    const float* Wih_w  = (const float*)d_in[13];
    const float* Whh_w  = (const float*)d_in[14];
    const float* bih_w  = (const float*)d_in[15];
    const float* bhh_w  = (const float*)d_in[16];
    const float* hn_w   = (const float*)d_in[17];
    const float* cn_w   = (const float*)d_in[18];
    const float* Wphi   = (const float*)d_in[19];
    const float* Wc     = (const float*)d_in[20];
    const float* bc     = (const float*)d_in[21];
    const float* states = (const float*)d_in[22];
    const float* goals  = (const float*)d_in[23];
    const int*   tick   = (const int*)d_in[24];
    float* out = (float*)d_out;

    k1<<<1872, 256>>>(x, Wp, bp, Wms, bms, Wih_w, Whh_w, bih_w, bhh_w,
                      hn_w, cn_w, Whh_m, bih_m, bhh_m, hn_m, goals, tick);
    k2<<<1026, 256>>>(Wih_m, goals, states, Wc, bc);
    k3<<<1, 1024>>>(hn_m, cn_m, Wmv, Wphi, states, bmv, tick, out);
}